// round 4
// baseline (speedup 1.0000x reference)
#include <cuda_runtime.h>

#define NN 32
#define CC 1024
#define NT 1024

// dynamic smem layout
#define OFF_ROWS 0                      // float [32][1024]  = 131072
#define OFF_D    131072                 // float [32][32]    = 4096
#define OFF_RED  135168                 // u64   [32]        = 256
#define OFF_SQ   135424                 // float [32]        = 128
#define OFF_FRED 135552                 // float [32]        = 128
#define OFF_DOT  135680                 // float [32]        = 128
#define OFF_L    135808                 // int   [32]        = 128
#define SMEM_TOTAL 135936

__device__ __forceinline__ float warp_sum(float v) {
    #pragma unroll
    for (int o = 16; o; o >>= 1) v += __shfl_down_sync(0xffffffffu, v, o);
    return v;
}

// four interleaved warp reductions (independent chains pipeline the SHFL latency)
__device__ __forceinline__ void warp_sum4(float& a, float& b, float& c, float& d) {
    #pragma unroll
    for (int o = 16; o; o >>= 1) {
        a += __shfl_down_sync(0xffffffffu, a, o);
        b += __shfl_down_sync(0xffffffffu, b, o);
        c += __shfl_down_sync(0xffffffffu, c, o);
        d += __shfl_down_sync(0xffffffffu, d, o);
    }
}

__device__ __forceinline__ void warp_sum2(float& a, float& b) {
    #pragma unroll
    for (int o = 16; o; o >>= 1) {
        a += __shfl_down_sync(0xffffffffu, a, o);
        b += __shfl_down_sync(0xffffffffu, b, o);
    }
}

__global__ __launch_bounds__(NT, 1)
void merge_tree_kernel(const float* __restrict__ x,
                       const float* __restrict__ cw,
                       const float* __restrict__ cb,
                       float* __restrict__ out)
{
    extern __shared__ unsigned char sm_raw[];
    float*  rows = (float*)(sm_raw + OFF_ROWS);
    float*  D    = (float*)(sm_raw + OFF_D);
    unsigned long long* red = (unsigned long long*)(sm_raw + OFF_RED);
    float*  sq   = (float*)(sm_raw + OFF_SQ);
    float*  fred = (float*)(sm_raw + OFF_FRED);
    float*  dotb = (float*)(sm_raw + OFF_DOT);
    int*    L    = (int*)(sm_raw + OFF_L);

    const int tid  = threadIdx.x;
    const int lane = tid & 31;
    const int warp = tid >> 5;
    const int b    = blockIdx.x;

    // ---- load batch rows (coalesced float4) ----
    {
        const float4* xb4 = (const float4*)(x + (size_t)b * (NN * CC));
        float4* r4 = (float4*)rows;
        #pragma unroll
        for (int i = tid; i < NN * CC / 4; i += NT) r4[i] = xb4[i];
    }
    const float w00 = cw[0], w01 = cw[1], w02 = cw[2];
    const float w10 = cw[3], w11 = cw[4], w12 = cw[5];
    const float bv  = cb[0];
    if (tid < NN) L[tid] = tid;
    __syncthreads();

    // ==== initial gram with 2x2 register tiling ====
    // warp w: super-row I = w>>1 (rows 2I, 2I+1), half = w&1 splits the J range
    {
        const int I = warp >> 1, half = warp & 1;
        float4 c0[8], c1[8];
        {
            const float4* r0 = (const float4*)(rows + (2 * I) * CC);
            const float4* r1 = (const float4*)(rows + (2 * I + 1) * CC);
            #pragma unroll
            for (int k = 0; k < 8; k++) {
                c0[k] = r0[lane + 32 * k];
                c1[k] = r1[lane + 32 * k];
            }
        }

        // norms: half0 -> |2I|^2, half1 -> |2I+1|^2 (4-chain, same order as before)
        float diagdot;   // dot(2I, 2I+1), computed by half0
        if (half == 0) {
            float a0 = 0, a1 = 0, a2 = 0, a3 = 0;
            #pragma unroll
            for (int k = 0; k < 8; k++) {
                a0 = fmaf(c0[k].x, c0[k].x, a0);
                a1 = fmaf(c0[k].y, c0[k].y, a1);
                a2 = fmaf(c0[k].z, c0[k].z, a2);
                a3 = fmaf(c0[k].w, c0[k].w, a3);
            }
            float s = warp_sum((a0 + a1) + (a2 + a3));
            if (!lane) sq[2 * I] = s;
            // diagonal pair dot
            float d0 = 0, d1 = 0, d2 = 0, d3 = 0;
            #pragma unroll
            for (int k = 0; k < 8; k++) {
                d0 = fmaf(c0[k].x, c1[k].x, d0);
                d1 = fmaf(c0[k].y, c1[k].y, d1);
                d2 = fmaf(c0[k].z, c1[k].z, d2);
                d3 = fmaf(c0[k].w, c1[k].w, d3);
            }
            diagdot = warp_sum((d0 + d1) + (d2 + d3));
        } else {
            float a0 = 0, a1 = 0, a2 = 0, a3 = 0;
            #pragma unroll
            for (int k = 0; k < 8; k++) {
                a0 = fmaf(c1[k].x, c1[k].x, a0);
                a1 = fmaf(c1[k].y, c1[k].y, a1);
                a2 = fmaf(c1[k].z, c1[k].z, a2);
                a3 = fmaf(c1[k].w, c1[k].w, a3);
            }
            float s = warp_sum((a0 + a1) + (a2 + a3));
            if (!lane) sq[2 * I + 1] = s;
            diagdot = 0.f;
        }
        __syncthreads();                       // sq[] visible

        if (half == 0 && !lane) {
            int i = 2 * I, j = 2 * I + 1;
            float d2v = sq[i] + sq[j] - 2.0f * diagdot;
            float d = sqrtf(fmaxf(d2v, 0.f));
            D[i * NN + j] = d;
            D[j * NN + i] = d;
        }

        // off-diagonal tiles: J = I+1+half, I+3+half, ...
        for (int J = I + 1 + half; J < 16; J += 2) {
            const float4* v0p = (const float4*)(rows + (2 * J) * CC);
            const float4* v1p = (const float4*)(rows + (2 * J + 1) * CC);
            float p00a=0,p00b=0,p00c=0,p00d=0;
            float p01a=0,p01b=0,p01c=0,p01d=0;
            float p10a=0,p10b=0,p10c=0,p10d=0;
            float p11a=0,p11b=0,p11c=0,p11d=0;
            #pragma unroll
            for (int k = 0; k < 8; k++) {
                float4 v0 = v0p[lane + 32 * k];
                float4 v1 = v1p[lane + 32 * k];
                p00a = fmaf(c0[k].x, v0.x, p00a);
                p00b = fmaf(c0[k].y, v0.y, p00b);
                p00c = fmaf(c0[k].z, v0.z, p00c);
                p00d = fmaf(c0[k].w, v0.w, p00d);
                p01a = fmaf(c0[k].x, v1.x, p01a);
                p01b = fmaf(c0[k].y, v1.y, p01b);
                p01c = fmaf(c0[k].z, v1.z, p01c);
                p01d = fmaf(c0[k].w, v1.w, p01d);
                p10a = fmaf(c1[k].x, v0.x, p10a);
                p10b = fmaf(c1[k].y, v0.y, p10b);
                p10c = fmaf(c1[k].z, v0.z, p10c);
                p10d = fmaf(c1[k].w, v0.w, p10d);
                p11a = fmaf(c1[k].x, v1.x, p11a);
                p11b = fmaf(c1[k].y, v1.y, p11b);
                p11c = fmaf(c1[k].z, v1.z, p11c);
                p11d = fmaf(c1[k].w, v1.w, p11d);
            }
            float s00 = (p00a + p00b) + (p00c + p00d);
            float s01 = (p01a + p01b) + (p01c + p01d);
            float s10 = (p10a + p10b) + (p10c + p10d);
            float s11 = (p11a + p11b) + (p11c + p11d);
            warp_sum4(s00, s01, s10, s11);
            if (!lane) {
                int i0 = 2 * I, i1 = 2 * I + 1, j0 = 2 * J, j1 = 2 * J + 1;
                float e00 = sqrtf(fmaxf(sq[i0] + sq[j0] - 2.0f * s00, 0.f));
                float e01 = sqrtf(fmaxf(sq[i0] + sq[j1] - 2.0f * s01, 0.f));
                float e10 = sqrtf(fmaxf(sq[i1] + sq[j0] - 2.0f * s10, 0.f));
                float e11 = sqrtf(fmaxf(sq[i1] + sq[j1] - 2.0f * s11, 0.f));
                D[i0 * NN + j0] = e00; D[j0 * NN + i0] = e00;
                D[i0 * NN + j1] = e01; D[j1 * NN + i0] = e01;
                D[i1 * NN + j0] = e10; D[j0 * NN + i1] = e10;
                D[i1 * NN + j1] = e11; D[j1 * NN + i1] = e11;
            }
        }
    }
    __syncthreads();                           // D complete

    // ==== 31 merge steps ====
    int n = NN;
    const int pi = tid >> 5;                   // argmin pair grid: i=warp, j=lane
    const int pj = tid & 31;
    for (int step = 0; step < NN - 1; step++, n--) {
        // -- P1: argmin (value, then lexicographic (i,j)) --
        unsigned long long key = 0xffffffffffffffffull;
        if (pi < pj && pj < n) {
            float d = D[L[pi] * NN + L[pj]];
            key = ((unsigned long long)__float_as_uint(d) << 32)
                | (unsigned)((pi << 5) | pj);
        }
        #pragma unroll
        for (int o = 16; o; o >>= 1) {
            unsigned long long t = __shfl_xor_sync(0xffffffffu, key, o);
            key = min(key, t);
        }
        if (!lane) red[warp] = key;
        __syncthreads();                       // bar A
        {   // every warp redundantly reduces the 32 partials (no 2nd bar)
            unsigned long long v = red[lane];
            #pragma unroll
            for (int o = 16; o; o >>= 1) {
                unsigned long long t = __shfl_xor_sync(0xffffffffu, v, o);
                v = min(v, t);
            }
            key = v;                           // all lanes hold global min
        }
        const unsigned k32 = (unsigned)key;
        const int a   = (k32 >> 5) & 31;
        const int bbj = k32 & 31;
        const int ra  = L[a];
        const int rb  = L[bbj];
        const int dst = L[(a == 1) ? 0 : a];   // freed slot hosts merged row

        // -- P2: conv1d(2ch->1ch,k=3,SAME)+bias+relu, norm partials, new L --
        const float* Xa = rows + ra * CC;
        const float* Xb = rows + rb * CC;
        const int h = tid;
        float a1v = Xa[h], b1v = Xb[h];
        float a0v = (h > 0)      ? Xa[h - 1] : 0.f;
        float a2v = (h < CC - 1) ? Xa[h + 1] : 0.f;
        float b0v = (h > 0)      ? Xb[h - 1] : 0.f;
        float b2v = (h < CC - 1) ? Xb[h + 1] : 0.f;
        float m = fmaf(w00, a0v, fmaf(w01, a1v, fmaf(w02, a2v,
                  fmaf(w10, b0v, fmaf(w11, b1v, fmaf(w12, b2v, bv))))));
        m = fmaxf(m, 0.f);

        float p2 = warp_sum(m * m);
        if (!lane) fred[warp] = p2;

        int newv = 0;
        if (tid < n - 1) {
            if (tid == 0) newv = dst;
            else {
                int pp  = tid + 1;
                int src = (pp == a) ? 0 : ((pp == bbj) ? 1 : pp);
                newv = L[src];
            }
        }
        __syncthreads();                       // bar B: rows/L reads done

        // -- P3: commit merged row + new map --
        rows[dst * CC + h] = m;
        if (tid < n - 1) L[tid] = newv;
        __syncthreads();                       // bar C: rows[dst], L, fred visible

        // -- P4: survivor dots (warps 0..14, 2 each, m chunk cached) ;
        //        warp 15 finalizes |m|^2 --
        const int cnt = n - 2;                 // survivors = new logical 1..n-2
        if (warp < 15) {
            const int j0 = warp, j1 = warp + 15;
            if (j0 < cnt) {
                float4 mv[8];
                const float4* rm = (const float4*)(rows + dst * CC);
                #pragma unroll
                for (int k = 0; k < 8; k++) mv[k] = rm[lane + 32 * k];

                const int s0 = L[1 + j0];
                const int s1 = L[1 + ((j1 < cnt) ? j1 : j0)];
                const float4* r0 = (const float4*)(rows + s0 * CC);
                const float4* r1 = (const float4*)(rows + s1 * CC);
                float q0a=0,q0b=0,q0c=0,q0d=0;
                float q1a=0,q1b=0,q1c=0,q1d=0;
                #pragma unroll
                for (int k = 0; k < 8; k++) {
                    float4 u = mv[k];
                    float4 v0 = r0[lane + 32 * k];
                    float4 v1 = r1[lane + 32 * k];
                    q0a = fmaf(u.x, v0.x, q0a);
                    q0b = fmaf(u.y, v0.y, q0b);
                    q0c = fmaf(u.z, v0.z, q0c);
                    q0d = fmaf(u.w, v0.w, q0d);
                    q1a = fmaf(u.x, v1.x, q1a);
                    q1b = fmaf(u.y, v1.y, q1b);
                    q1c = fmaf(u.z, v1.z, q1c);
                    q1d = fmaf(u.w, v1.w, q1d);
                }
                float t0 = (q0a + q0b) + (q0c + q0d);
                float t1 = (q1a + q1b) + (q1c + q1d);
                warp_sum2(t0, t1);
                if (!lane) {
                    dotb[j0] = t0;
                    if (j1 < cnt) dotb[j1] = t1;
                }
            }
        } else if (warp == 15) {
            float s = fred[lane];
            s = warp_sum(s);
            if (!lane) sq[dst] = s;
        }
        __syncthreads();                       // bar D: dotb, sq[dst] visible

        // -- P5: finalize distances for merged row --
        if (tid < cnt) {
            const int s = L[1 + tid];
            float d2 = sq[dst] + sq[s] - 2.0f * dotb[tid];
            float d  = sqrtf(fmaxf(d2, 0.f));
            D[dst * NN + s] = d;
            D[s * NN + dst] = d;
        }
        __syncthreads();                       // bar E: D ready for next argmin
    }

    // final merged row lives at slot L[0]
    out[(size_t)b * CC + tid] = rows[L[0] * CC + tid];
}

extern "C" void kernel_launch(void* const* d_in, const int* in_sizes, int n_in,
                              void* d_out, int out_size)
{
    const float* x  = (const float*)d_in[0];
    const float* cw = (const float*)d_in[1];
    const float* cb = (const float*)d_in[2];
    float* out = (float*)d_out;

    int B = in_sizes[0] / (NN * CC);

    cudaFuncSetAttribute(merge_tree_kernel,
                         cudaFuncAttributeMaxDynamicSharedMemorySize,
                         SMEM_TOTAL);
    merge_tree_kernel<<<B, NT, SMEM_TOTAL>>>(x, cw, cb, out);
}

// round 5
// speedup vs baseline: 1.3181x; 1.3181x over previous
#include <cuda_runtime.h>

#define NN 32
#define CC 1024
#define NT 1024

// dynamic smem layout
#define OFF_ROWS 0                      // float [32][1024]  = 131072
#define OFF_D    131072                 // float [32][32]    = 4096
#define OFF_VAL  135168                 // u32   [32]        = 128
#define OFF_IDX  135296                 // u32   [32]        = 128
#define OFF_SQ   135424                 // float [32]        = 128
#define OFF_L    135552                 // int   [32]        = 128
#define SMEM_TOTAL 135680

__device__ __forceinline__ float warp_sum(float v) {
    #pragma unroll
    for (int o = 16; o; o >>= 1) v += __shfl_down_sync(0xffffffffu, v, o);
    return v;
}

// two interleaved warp reductions (independent chains pipeline SHFL latency)
__device__ __forceinline__ void warp_sum2(float& a, float& b) {
    #pragma unroll
    for (int o = 16; o; o >>= 1) {
        a += __shfl_down_sync(0xffffffffu, a, o);
        b += __shfl_down_sync(0xffffffffu, b, o);
    }
}

__global__ __launch_bounds__(NT, 1)
void merge_tree_kernel(const float* __restrict__ x,
                       const float* __restrict__ cw,
                       const float* __restrict__ cb,
                       float* __restrict__ out)
{
    extern __shared__ unsigned char sm_raw[];
    float*    rows = (float*)(sm_raw + OFF_ROWS);
    float*    D    = (float*)(sm_raw + OFF_D);
    unsigned* vals = (unsigned*)(sm_raw + OFF_VAL);
    unsigned* idxs = (unsigned*)(sm_raw + OFF_IDX);
    float*    sq   = (float*)(sm_raw + OFF_SQ);
    int*      L    = (int*)(sm_raw + OFF_L);

    const int tid  = threadIdx.x;
    const int lane = tid & 31;
    const int warp = tid >> 5;
    const int b    = blockIdx.x;

    // ---- load batch rows (coalesced float4) ----
    {
        const float4* xb4 = (const float4*)(x + (size_t)b * (NN * CC));
        float4* r4 = (float4*)rows;
        #pragma unroll
        for (int i = tid; i < NN * CC / 4; i += NT) r4[i] = xb4[i];
    }
    const float w00 = cw[0], w01 = cw[1], w02 = cw[2];
    const float w10 = cw[3], w11 = cw[4], w12 = cw[5];
    const float bv  = cb[0];
    if (tid < NN) L[tid] = tid;
    __syncthreads();

    // ---- cache own row in registers; norms (fp32, 4-chain) ----
    float4 rv[8];
    {
        const float4* r4w = (const float4*)(rows + warp * CC);
        #pragma unroll
        for (int k = 0; k < 8; k++) rv[k] = r4w[lane + 32 * k];
        float a0 = 0, a1 = 0, a2 = 0, a3 = 0;
        #pragma unroll
        for (int k = 0; k < 8; k++) {
            a0 = fmaf(rv[k].x, rv[k].x, a0);
            a1 = fmaf(rv[k].y, rv[k].y, a1);
            a2 = fmaf(rv[k].z, rv[k].z, a2);
            a3 = fmaf(rv[k].w, rv[k].w, a3);
        }
        float s = warp_sum((a0 + a1) + (a2 + a3));
        if (!lane) sq[warp] = s;
    }
    __syncthreads();

    // ---- initial gram: warp i vs all j>i, row i register-cached ----
    {
        const float sqi = sq[warp];
        for (int j = warp + 1; j < NN; j++) {
            const float4* rj4 = (const float4*)(rows + j * CC);
            float a0 = 0, a1 = 0, a2 = 0, a3 = 0;
            #pragma unroll
            for (int k = 0; k < 8; k++) {
                float4 v = rj4[lane + 32 * k];
                a0 = fmaf(rv[k].x, v.x, a0);
                a1 = fmaf(rv[k].y, v.y, a1);
                a2 = fmaf(rv[k].z, v.z, a2);
                a3 = fmaf(rv[k].w, v.w, a3);
            }
            float dot = warp_sum((a0 + a1) + (a2 + a3));
            if (!lane) {
                float d2 = sqi + sq[j] - 2.0f * dot;
                float d  = sqrtf(fmaxf(d2, 0.f));
                D[warp * NN + j] = d;
                D[j * NN + warp] = d;
            }
        }
    }
    __syncthreads();

    // ==== 31 merge steps, 4 barriers each ====
    int n = NN;
    const int pi = warp;              // argmin pair grid: i = warp, j = lane
    const int pj = lane;
    for (int step = 0; step < NN - 1; step++, n--) {
        // -- P1: argmin via REDUX + ballot (value, lexicographic tie-break) --
        unsigned dv = 0xffffffffu;    // +inf sentinel (bit order of nonneg f32)
        if (pi < pj && pj < n) dv = __float_as_uint(D[L[pi] * NN + L[pj]]);
        unsigned wmin = __reduce_min_sync(0xffffffffu, dv);
        unsigned bal  = __ballot_sync(0xffffffffu, dv == wmin);
        if (!lane) {
            int jw = __ffs(bal) - 1;            // lowest lane = smallest j
            vals[warp] = wmin;
            idxs[warp] = (unsigned)((pi << 5) | jw);
        }
        __syncthreads();                         // bar A

        unsigned v  = vals[lane];
        unsigned gm = __reduce_min_sync(0xffffffffu, v);
        unsigned b2 = __ballot_sync(0xffffffffu, v == gm);
        const unsigned k32 = idxs[__ffs(b2) - 1]; // lowest warp = smallest i

        const int a   = (k32 >> 5) & 31;
        const int bbj = k32 & 31;
        const int ra  = L[a];
        const int rb  = L[bbj];
        const int dst = L[(a == 1) ? 0 : a];     // freed slot hosts merged row

        // -- P2: conv1d(2ch->1ch,k=3,SAME)+bias+relu; new L from old L --
        const float* Xa = rows + ra * CC;
        const float* Xb = rows + rb * CC;
        const int h = tid;
        float a1v = Xa[h], b1v = Xb[h];
        float a0v = (h > 0)      ? Xa[h - 1] : 0.f;
        float a2v = (h < CC - 1) ? Xa[h + 1] : 0.f;
        float b0v = (h > 0)      ? Xb[h - 1] : 0.f;
        float b2v = (h < CC - 1) ? Xb[h + 1] : 0.f;
        float m = fmaf(w00, a0v, fmaf(w01, a1v, fmaf(w02, a2v,
                  fmaf(w10, b0v, fmaf(w11, b1v, fmaf(w12, b2v, bv))))));
        m = fmaxf(m, 0.f);

        int newv = 0;
        if (tid < n - 1) {
            if (tid == 0) newv = dst;
            else {
                int pp  = tid + 1;
                int src = (pp == a) ? 0 : ((pp == bbj) ? 1 : pp);
                newv = L[src];
            }
        }
        __syncthreads();                         // bar B: rows/L reads done

        // -- P3: commit merged row + new logical map --
        rows[dst * CC + h] = m;
        if (tid < n - 1) L[tid] = newv;
        __syncthreads();                         // bar C

        // -- P4: one survivor dot per warp; each warp also reduces |m|^2
        //        from the merged chunk it already loads, then writes D --
        const int cnt = n - 2;                   // survivors = new logical 1..n-2
        if (warp < cnt) {
            const int s = L[1 + warp];
            const float4* rm = (const float4*)(rows + dst * CC);
            const float4* rs = (const float4*)(rows + s * CC);
            float A0 = 0, A1 = 0, A2 = 0, A3 = 0;  // dot(m, survivor)
            float M0 = 0, M1 = 0, M2 = 0, M3 = 0;  // |m|^2
            #pragma unroll
            for (int k = 0; k < 8; k++) {
                float4 u = rm[lane + 32 * k];
                float4 w = rs[lane + 32 * k];
                A0 = fmaf(u.x, w.x, A0);
                A1 = fmaf(u.y, w.y, A1);
                A2 = fmaf(u.z, w.z, A2);
                A3 = fmaf(u.w, w.w, A3);
                M0 = fmaf(u.x, u.x, M0);
                M1 = fmaf(u.y, u.y, M1);
                M2 = fmaf(u.z, u.z, M2);
                M3 = fmaf(u.w, u.w, M3);
            }
            float dot = (A0 + A1) + (A2 + A3);
            float msq = (M0 + M1) + (M2 + M3);
            warp_sum2(dot, msq);
            if (!lane) {
                float d2 = msq + sq[s] - 2.0f * dot;
                float d  = sqrtf(fmaxf(d2, 0.f));
                D[dst * NN + s] = d;
                D[s * NN + dst] = d;
                if (warp == 0) sq[dst] = msq;    // persist merged norm
            }
        }
        __syncthreads();                         // bar E: D, sq, ready for next argmin
    }

    // final merged row lives at slot L[0]
    out[(size_t)b * CC + tid] = rows[L[0] * CC + tid];
}

extern "C" void kernel_launch(void* const* d_in, const int* in_sizes, int n_in,
                              void* d_out, int out_size)
{
    const float* x  = (const float*)d_in[0];
    const float* cw = (const float*)d_in[1];
    const float* cb = (const float*)d_in[2];
    float* out = (float*)d_out;

    int B = in_sizes[0] / (NN * CC);

    cudaFuncSetAttribute(merge_tree_kernel,
                         cudaFuncAttributeMaxDynamicSharedMemorySize,
                         SMEM_TOTAL);
    merge_tree_kernel<<<B, NT, SMEM_TOTAL>>>(x, cw, cb, out);
}